// round 14
// baseline (speedup 1.0000x reference)
#include <cuda_runtime.h>

#define FDIM 128
#define DEG 16
#define MAXN 65536
#define EPS 1e-12f

// Scratch: per-node inverse L2 norm (allocation-free rule -> __device__ global)
__device__ float g_rn[MAXN];

__device__ __forceinline__ float warp_sum(float p) {
#pragma unroll
    for (int o = 16; o; o >>= 1) p += __shfl_xor_sync(0xffffffffu, p, o);
    return p;
}

__device__ __forceinline__ void prefetch_l1(const void* p) {
    asm volatile("prefetch.global.L1 [%0];" :: "l"(p));
}

// ---------------------------------------------------------------------------
// Kernel 1: per-node inverse norm. One warp per node, float4 per lane.
// ---------------------------------------------------------------------------
__global__ void norm_kernel(const float* __restrict__ x, int n) {
    int warp = (blockIdx.x * blockDim.x + threadIdx.x) >> 5;
    int lane = threadIdx.x & 31;
    if (warp >= n) return;
    const float4* xr = reinterpret_cast<const float4*>(x + (size_t)warp * FDIM);
    float4 v = xr[lane];
    float s = warp_sum(v.x * v.x + v.y * v.y + v.z * v.z + v.w * v.w);
    if (lane == 0) g_rn[warp] = rsqrtf(s + EPS);
}

// ---------------------------------------------------------------------------
// Kernel 2: AGNN, one warp per node, neighbors in QUADS (R7 body) plus
// NEXT-QUAD L1 PREFETCH: while computing quad qd, prefetch quad qd+1's rows
// so its gathers hit L1 (~39cyc) instead of L2 (~250cyc). Prefetch index regs
// die before the compute section -> peak liveness (and occupancy) unchanged.
// ---------------------------------------------------------------------------
__global__ __launch_bounds__(256, 6) void agnn_kernel(
    const float* __restrict__ x,
    const int*   __restrict__ col_id,
    const float* __restrict__ beta,
    float*       __restrict__ out,
    int n)
{
    int warp = (blockIdx.x * blockDim.x + threadIdx.x) >> 5;
    int lane = threadIdx.x & 31;
    if (warp >= n) return;

    float b    = beta[0];
    float babs = fabsf(b);
    bool  b4   = (lane & 16) != 0;
    bool  b3   = (lane & 8)  != 0;

    const float4* xv = reinterpret_cast<const float4*>(x);   // row = 32 float4
    float4 vi = xv[((unsigned)warp << 5) + lane];
    float  kq = b * g_rn[warp];
    float4 vip = make_float4(vi.x * kq, vi.y * kq, vi.z * kq, vi.w * kq);

    // Fixed degree: this node's 16 indices start at warp*DEG (64B aligned).
    const int4* cidx = reinterpret_cast<const int4*>(col_id) + ((unsigned)warp << 2);

    float  s   = 0.0f;
    float4 acc = make_float4(0.f, 0.f, 0.f, 0.f);

#pragma unroll
    for (int qd = 0; qd < DEG / 4; qd++) {
        int4 c = __ldg(&cidx[qd]);
        float4 v0 = xv[((unsigned)c.x << 5) + lane];
        float4 v1 = xv[((unsigned)c.y << 5) + lane];
        float4 v2 = xv[((unsigned)c.z << 5) + lane];
        float4 v3 = xv[((unsigned)c.w << 5) + lane];

        // Prefetch next quad's rows into L1 (cn dead before compute below).
        if (qd < DEG / 4 - 1) {
            int4 cn = __ldg(&cidx[qd + 1]);
            prefetch_l1(&xv[((unsigned)cn.x << 5) + lane]);
            prefetch_l1(&xv[((unsigned)cn.y << 5) + lane]);
            prefetch_l1(&xv[((unsigned)cn.z << 5) + lane]);
            prefetch_l1(&xv[((unsigned)cn.w << 5) + lane]);
        }

        // Group-owned neighbor id: (b4,b3) -> (0,0)=c.x (0,1)=c.z (1,0)=c.y (1,1)=c.w
        int   csel  = b4 ? (b3 ? c.w : c.y) : (b3 ? c.z : c.x);
        float rnsel = __ldg(&g_rn[csel]);   // 8-lane group shares one address

        float p0 = vip.x * v0.x + vip.y * v0.y + vip.z * v0.z + vip.w * v0.w;
        float p1 = vip.x * v1.x + vip.y * v1.y + vip.z * v1.z + vip.w * v1.w;
        float p2 = vip.x * v2.x + vip.y * v2.y + vip.z * v2.z + vip.w * v2.w;
        float p3 = vip.x * v3.x + vip.y * v3.y + vip.z * v3.z + vip.w * v3.w;

        // Fold at offset 16: low half keeps p0/p2 partials, high half p1/p3.
        float u = (b4 ? p1 : p0) + __shfl_xor_sync(0xffffffffu, b4 ? p0 : p1, 16);
        float v = (b4 ? p3 : p2) + __shfl_xor_sync(0xffffffffu, b4 ? p2 : p3, 16);
        // Fold at offset 8 -> each 8-lane group owns one neighbor's partial.
        float q = (b3 ? v : u) + __shfl_xor_sync(0xffffffffu, b3 ? u : v, 8);
        // Shared butterfly within 8-lane groups.
        q += __shfl_xor_sync(0xffffffffu, q, 4);
        q += __shfl_xor_sync(0xffffffffu, q, 2);
        q += __shfl_xor_sync(0xffffffffu, q, 1);

        float e = fmaf(q, rnsel, -babs);   // beta*cos - |beta| <= 0
        float w = __expf(e);

        float w0 = __shfl_sync(0xffffffffu, w, 0);
        float w2 = __shfl_sync(0xffffffffu, w, 8);
        float w1 = __shfl_sync(0xffffffffu, w, 16);
        float w3 = __shfl_sync(0xffffffffu, w, 24);

        s += (w0 + w1) + (w2 + w3);
        acc.x = fmaf(w0, v0.x, fmaf(w1, v1.x, fmaf(w2, v2.x, fmaf(w3, v3.x, acc.x))));
        acc.y = fmaf(w0, v0.y, fmaf(w1, v1.y, fmaf(w2, v2.y, fmaf(w3, v3.y, acc.y))));
        acc.z = fmaf(w0, v0.z, fmaf(w1, v1.z, fmaf(w2, v2.z, fmaf(w3, v3.z, acc.z))));
        acc.w = fmaf(w0, v0.w, fmaf(w1, v1.w, fmaf(w2, v2.w, fmaf(w3, v3.w, acc.w))));
    }

    float inv = 1.0f / s;
    float4 o = make_float4(acc.x * inv, acc.y * inv, acc.z * inv, acc.w * inv);
    reinterpret_cast<float4*>(out)[((unsigned)warp << 5) + lane] = o;
}

// ---------------------------------------------------------------------------
// Launch
// ---------------------------------------------------------------------------
extern "C" void kernel_launch(void* const* d_in, const int* in_sizes, int n_in,
                              void* d_out, int out_size) {
    const float* x       = (const float*)d_in[0];
    // d_in[1] = row_id (COO), d_in[2] = row_ptr — fixed degree, base = node*16
    const int*   col_id  = (const int*)d_in[3];
    const float* beta    = (const float*)d_in[4];
    float*       out     = (float*)d_out;

    int n = in_sizes[2] - 1;   // row_ptr has N+1 entries
    if (n > MAXN) n = MAXN;    // defensive: scratch bound (no-op for this shape)

    int threads = 256;
    int blocks  = (n * 32 + threads - 1) / threads;

    norm_kernel<<<blocks, threads>>>(x, n);
    agnn_kernel<<<blocks, threads>>>(x, col_id, beta, out, n);
}

// round 15
// speedup vs baseline: 1.1348x; 1.1348x over previous
#include <cuda_runtime.h>
#include <cuda_fp16.h>

#define FDIM 128
#define DEG 16
#define MAXN 65536
#define EPS 1e-12f

// Scratch (allocation-free rule -> __device__ globals):
//   g_rn : per-node inverse L2 norm (computed in fp32, exact)
//   g_xh : fp16 copy of x, row = 32 uint2 = 128 halves = 256B
__device__ float g_rn[MAXN];
__device__ uint2 g_xh[MAXN * 32];

__device__ __forceinline__ float warp_sum(float p) {
#pragma unroll
    for (int o = 16; o; o >>= 1) p += __shfl_xor_sync(0xffffffffu, p, o);
    return p;
}

__device__ __forceinline__ float4 h2f4(uint2 u) {
    __half2 h0 = *reinterpret_cast<__half2*>(&u.x);
    __half2 h1 = *reinterpret_cast<__half2*>(&u.y);
    float2 f0 = __half22float2(h0);
    float2 f1 = __half22float2(h1);
    return make_float4(f0.x, f0.y, f1.x, f1.y);
}

// ---------------------------------------------------------------------------
// Kernel 1: fp32 norms + fp16 feature cache. One warp per node.
// ---------------------------------------------------------------------------
__global__ void prep_kernel(const float* __restrict__ x, int n) {
    int warp = (blockIdx.x * blockDim.x + threadIdx.x) >> 5;
    int lane = threadIdx.x & 31;
    if (warp >= n) return;
    float4 v = reinterpret_cast<const float4*>(x)[((unsigned)warp << 5) + lane];
    float s = warp_sum(v.x * v.x + v.y * v.y + v.z * v.z + v.w * v.w);
    if (lane == 0) g_rn[warp] = rsqrtf(s + EPS);
    __half2 h0 = __floats2half2_rn(v.x, v.y);
    __half2 h1 = __floats2half2_rn(v.z, v.w);
    uint2 u;
    u.x = *reinterpret_cast<unsigned*>(&h0);
    u.y = *reinterpret_cast<unsigned*>(&h1);
    g_xh[((unsigned)warp << 5) + lane] = u;
}

// ---------------------------------------------------------------------------
// Kernel 2: AGNN, one warp per node, QUADS (R7 body) over fp16 rows:
//  - gathers halve to 256B/row (LDG.64/lane) -> half the L1/L2 traffic
//  - norms/softmax/accumulation in fp32; scores shifted by -|beta|
//  - quad-fold shuffle reduction; one __expf per lane per quad
// ---------------------------------------------------------------------------
__global__ __launch_bounds__(256, 6) void agnn_kernel(
    const int*   __restrict__ col_id,
    const float* __restrict__ beta,
    float*       __restrict__ out,
    int n)
{
    int warp = (blockIdx.x * blockDim.x + threadIdx.x) >> 5;
    int lane = threadIdx.x & 31;
    if (warp >= n) return;

    float b    = beta[0];
    float babs = fabsf(b);
    bool  b4   = (lane & 16) != 0;
    bool  b3   = (lane & 8)  != 0;

    float4 vi = h2f4(g_xh[((unsigned)warp << 5) + lane]);
    float  kq = b * g_rn[warp];
    float4 vip = make_float4(vi.x * kq, vi.y * kq, vi.z * kq, vi.w * kq);

    // Fixed degree: this node's 16 indices start at warp*DEG (64B aligned).
    const int4* cidx = reinterpret_cast<const int4*>(col_id) + ((unsigned)warp << 2);

    float  s   = 0.0f;
    float4 acc = make_float4(0.f, 0.f, 0.f, 0.f);

#pragma unroll
    for (int qd = 0; qd < DEG / 4; qd++) {
        int4 c = __ldg(&cidx[qd]);
        float4 v0 = h2f4(__ldg(&g_xh[((unsigned)c.x << 5) + lane]));
        float4 v1 = h2f4(__ldg(&g_xh[((unsigned)c.y << 5) + lane]));
        float4 v2 = h2f4(__ldg(&g_xh[((unsigned)c.z << 5) + lane]));
        float4 v3 = h2f4(__ldg(&g_xh[((unsigned)c.w << 5) + lane]));

        // Group-owned neighbor id: (b4,b3) -> (0,0)=c.x (0,1)=c.z (1,0)=c.y (1,1)=c.w
        int   csel  = b4 ? (b3 ? c.w : c.y) : (b3 ? c.z : c.x);
        float rnsel = __ldg(&g_rn[csel]);   // 8-lane group shares one address

        float p0 = vip.x * v0.x + vip.y * v0.y + vip.z * v0.z + vip.w * v0.w;
        float p1 = vip.x * v1.x + vip.y * v1.y + vip.z * v1.z + vip.w * v1.w;
        float p2 = vip.x * v2.x + vip.y * v2.y + vip.z * v2.z + vip.w * v2.w;
        float p3 = vip.x * v3.x + vip.y * v3.y + vip.z * v3.z + vip.w * v3.w;

        // Fold at offset 16: low half keeps p0/p2 partials, high half p1/p3.
        float u = (b4 ? p1 : p0) + __shfl_xor_sync(0xffffffffu, b4 ? p0 : p1, 16);
        float v = (b4 ? p3 : p2) + __shfl_xor_sync(0xffffffffu, b4 ? p2 : p3, 16);
        // Fold at offset 8 -> each 8-lane group owns one neighbor's partial.
        float q = (b3 ? v : u) + __shfl_xor_sync(0xffffffffu, b3 ? u : v, 8);
        // Shared butterfly within 8-lane groups.
        q += __shfl_xor_sync(0xffffffffu, q, 4);
        q += __shfl_xor_sync(0xffffffffu, q, 2);
        q += __shfl_xor_sync(0xffffffffu, q, 1);

        float e = fmaf(q, rnsel, -babs);   // ~beta*cos - |beta| <= ~0
        float w = __expf(e);

        float w0 = __shfl_sync(0xffffffffu, w, 0);
        float w2 = __shfl_sync(0xffffffffu, w, 8);
        float w1 = __shfl_sync(0xffffffffu, w, 16);
        float w3 = __shfl_sync(0xffffffffu, w, 24);

        s += (w0 + w1) + (w2 + w3);
        acc.x = fmaf(w0, v0.x, fmaf(w1, v1.x, fmaf(w2, v2.x, fmaf(w3, v3.x, acc.x))));
        acc.y = fmaf(w0, v0.y, fmaf(w1, v1.y, fmaf(w2, v2.y, fmaf(w3, v3.y, acc.y))));
        acc.z = fmaf(w0, v0.z, fmaf(w1, v1.z, fmaf(w2, v2.z, fmaf(w3, v3.z, acc.z))));
        acc.w = fmaf(w0, v0.w, fmaf(w1, v1.w, fmaf(w2, v2.w, fmaf(w3, v3.w, acc.w))));
    }

    float inv = 1.0f / s;
    float4 o = make_float4(acc.x * inv, acc.y * inv, acc.z * inv, acc.w * inv);
    reinterpret_cast<float4*>(out)[((unsigned)warp << 5) + lane] = o;
}

// ---------------------------------------------------------------------------
// Launch
// ---------------------------------------------------------------------------
extern "C" void kernel_launch(void* const* d_in, const int* in_sizes, int n_in,
                              void* d_out, int out_size) {
    const float* x       = (const float*)d_in[0];
    // d_in[1] = row_id (COO), d_in[2] = row_ptr — fixed degree, base = node*16
    const int*   col_id  = (const int*)d_in[3];
    const float* beta    = (const float*)d_in[4];
    float*       out     = (float*)d_out;

    int n = in_sizes[2] - 1;   // row_ptr has N+1 entries
    if (n > MAXN) n = MAXN;    // defensive: scratch bound (no-op for this shape)

    int threads = 256;
    int blocks  = (n * 32 + threads - 1) / threads;

    prep_kernel<<<blocks, threads>>>(x, n);
    agnn_kernel<<<blocks, threads>>>(col_id, beta, out, n);
}

// round 17
// speedup vs baseline: 1.1783x; 1.0384x over previous
#include <cuda_runtime.h>
#include <cuda_fp16.h>

#define FDIM 128
#define DEG 16
#define MAXN 65536
#define EPS 1e-12f
#define LOG2E 1.4426950408889634f

// Scratch (allocation-free rule -> __device__ globals):
//   g_rn : per-node inverse L2 norm (computed in fp32, exact)
//   g_xh : fp16 copy of x, row = 32 uint2 = 128 halves = 256B
__device__ float g_rn[MAXN];
__device__ uint2 g_xh[MAXN * 32];

__device__ __forceinline__ float warp_sum(float p) {
#pragma unroll
    for (int o = 16; o; o >>= 1) p += __shfl_xor_sync(0xffffffffu, p, o);
    return p;
}

__device__ __forceinline__ float4 h2f4(uint2 u) {
    __half2 h0 = *reinterpret_cast<__half2*>(&u.x);
    __half2 h1 = *reinterpret_cast<__half2*>(&u.y);
    float2 f0 = __half22float2(h0);
    float2 f1 = __half22float2(h1);
    return make_float4(f0.x, f0.y, f1.x, f1.y);
}

// ---------------------------------------------------------------------------
// Kernel 1: fp32 norms + fp16 feature cache. One warp per node.
// ---------------------------------------------------------------------------
__global__ void prep_kernel(const float* __restrict__ x, int n) {
    int warp = (blockIdx.x * blockDim.x + threadIdx.x) >> 5;
    int lane = threadIdx.x & 31;
    if (warp >= n) return;
    float4 v = reinterpret_cast<const float4*>(x)[((unsigned)warp << 5) + lane];
    float s = warp_sum(v.x * v.x + v.y * v.y + v.z * v.z + v.w * v.w);
    if (lane == 0) g_rn[warp] = rsqrtf(s + EPS);
    __half2 h0 = __floats2half2_rn(v.x, v.y);
    __half2 h1 = __floats2half2_rn(v.z, v.w);
    uint2 u;
    u.x = *reinterpret_cast<unsigned*>(&h0);
    u.y = *reinterpret_cast<unsigned*>(&h1);
    g_xh[((unsigned)warp << 5) + lane] = u;
}

// ---------------------------------------------------------------------------
// Kernel 2: AGNN, one warp per node, QUADS over fp16 rows.
//  - neighbor norms preloaded to registers (lane j holds rn of neighbor j&15):
//    per-quad rnsel = one SHFL instead of an LDG on the critical chain
//  - log2e folded into query scale -> w = exp2f(fma(q, rnsel, -babs2))
//  - quad-fold shuffle reduction; fp32 softmax/accumulation
// ---------------------------------------------------------------------------
__global__ __launch_bounds__(256, 6) void agnn_kernel(
    const int*   __restrict__ col_id,
    const float* __restrict__ beta,
    float*       __restrict__ out,
    int n)
{
    int warp = (blockIdx.x * blockDim.x + threadIdx.x) >> 5;
    int lane = threadIdx.x & 31;
    if (warp >= n) return;

    float b     = beta[0];
    float babs2 = fabsf(b) * LOG2E;
    bool  b4    = (lane & 16) != 0;
    bool  b3    = (lane & 8)  != 0;
    // fold-result position of this 8-lane group within a quad:
    // (b4,b3): (0,0)->neighbor0 (0,1)->2 (1,0)->1 (1,1)->3
    int groupoff = b4 ? (b3 ? 3 : 1) : (b3 ? 2 : 0);

    // Prologue: lane j holds neighbor (j&15)'s id and inverse norm.
    int   cj  = __ldg(&col_id[((unsigned)warp << 4) + (lane & 15)]);
    float rnj = __ldg(&g_rn[cj]);

    float4 vi = h2f4(g_xh[((unsigned)warp << 5) + lane]);
    float  kq = b * g_rn[warp] * LOG2E;
    float4 vip = make_float4(vi.x * kq, vi.y * kq, vi.z * kq, vi.w * kq);

    // Fixed degree: this node's 16 indices start at warp*DEG (64B aligned).
    const int4* cidx = reinterpret_cast<const int4*>(col_id) + ((unsigned)warp << 2);

    float  s   = 0.0f;
    float4 acc = make_float4(0.f, 0.f, 0.f, 0.f);

#pragma unroll
    for (int qd = 0; qd < DEG / 4; qd++) {
        int4 c = __ldg(&cidx[qd]);
        float4 v0 = h2f4(__ldg(&g_xh[((unsigned)c.x << 5) + lane]));
        float4 v1 = h2f4(__ldg(&g_xh[((unsigned)c.y << 5) + lane]));
        float4 v2 = h2f4(__ldg(&g_xh[((unsigned)c.z << 5) + lane]));
        float4 v3 = h2f4(__ldg(&g_xh[((unsigned)c.w << 5) + lane]));

        // Group's neighbor norm from the preloaded register (no LDG).
        float rnsel = __shfl_sync(0xffffffffu, rnj, qd * 4 + groupoff);

        float p0 = vip.x * v0.x + vip.y * v0.y + vip.z * v0.z + vip.w * v0.w;
        float p1 = vip.x * v1.x + vip.y * v1.y + vip.z * v1.z + vip.w * v1.w;
        float p2 = vip.x * v2.x + vip.y * v2.y + vip.z * v2.z + vip.w * v2.w;
        float p3 = vip.x * v3.x + vip.y * v3.y + vip.z * v3.z + vip.w * v3.w;

        // Fold at offset 16: low half keeps p0/p2 partials, high half p1/p3.
        float u = (b4 ? p1 : p0) + __shfl_xor_sync(0xffffffffu, b4 ? p0 : p1, 16);
        float v = (b4 ? p3 : p2) + __shfl_xor_sync(0xffffffffu, b4 ? p2 : p3, 16);
        // Fold at offset 8 -> each 8-lane group owns one neighbor's partial.
        float q = (b3 ? v : u) + __shfl_xor_sync(0xffffffffu, b3 ? u : v, 8);
        // Shared butterfly within 8-lane groups.
        q += __shfl_xor_sync(0xffffffffu, q, 4);
        q += __shfl_xor_sync(0xffffffffu, q, 2);
        q += __shfl_xor_sync(0xffffffffu, q, 1);

        // q carries beta*rni*log2e; e2 = log2e*(beta*cos - |beta|) <= ~0
        float e2 = fmaf(q, rnsel, -babs2);
        float w  = exp2f(e2);

        float w0 = __shfl_sync(0xffffffffu, w, 0);
        float w2 = __shfl_sync(0xffffffffu, w, 8);
        float w1 = __shfl_sync(0xffffffffu, w, 16);
        float w3 = __shfl_sync(0xffffffffu, w, 24);

        s += (w0 + w1) + (w2 + w3);
        acc.x = fmaf(w0, v0.x, fmaf(w1, v1.x, fmaf(w2, v2.x, fmaf(w3, v3.x, acc.x))));
        acc.y = fmaf(w0, v0.y, fmaf(w1, v1.y, fmaf(w2, v2.y, fmaf(w3, v3.y, acc.y))));
        acc.z = fmaf(w0, v0.z, fmaf(w1, v1.z, fmaf(w2, v2.z, fmaf(w3, v3.z, acc.z))));
        acc.w = fmaf(w0, v0.w, fmaf(w1, v1.w, fmaf(w2, v2.w, fmaf(w3, v3.w, acc.w))));
    }

    float inv = 1.0f / s;
    float4 o = make_float4(acc.x * inv, acc.y * inv, acc.z * inv, acc.w * inv);
    reinterpret_cast<float4*>(out)[((unsigned)warp << 5) + lane] = o;
}

// ---------------------------------------------------------------------------
// Launch
// ---------------------------------------------------------------------------
extern "C" void kernel_launch(void* const* d_in, const int* in_sizes, int n_in,
                              void* d_out, int out_size) {
    const float* x       = (const float*)d_in[0];
    // d_in[1] = row_id (COO), d_in[2] = row_ptr — fixed degree, base = node*16
    const int*   col_id  = (const int*)d_in[3];
    const float* beta    = (const float*)d_in[4];
    float*       out     = (float*)d_out;

    int n = in_sizes[2] - 1;   // row_ptr has N+1 entries
    if (n > MAXN) n = MAXN;    // defensive: scratch bound (no-op for this shape)

    int threads = 256;
    int blocks  = (n * 32 + threads - 1) / threads;

    prep_kernel<<<blocks, threads>>>(x, n);
    agnn_kernel<<<blocks, threads>>>(col_id, beta, out, n);
}